// round 8
// baseline (speedup 1.0000x reference)
#include <cuda_runtime.h>
#include <cuda_bf16.h>
#include <cstdint>
#include <math.h>

#define BATCH 16
#define HID   1024
#define G4    (4*HID)
#define TSTEPS 257
#define TPAD  272
#define VOC   1024
#define EMB   512
#define SEQ   512
#define ENC2D 1024
#define SOS_TOK 1
#define EOS_TOK 2
#define NTHR 256

typedef unsigned long long u64;
typedef unsigned int u32;

#define WB_B0 0u
#define WB_B1 4194304u
#define WB_B2 12582912u
#define WB_TOT 20971520u

// ---------------- device scratch ----------------
__device__ float g_P0[VOC * G4];
__device__ __align__(16) __nv_bfloat16 g_Wb[WB_TOT];
__device__ __align__(16) __nv_bfloat16 g_hb[3][BATCH * HID];
__device__ float g_hs[TSTEPS * BATCH * HID];
__device__ float g_ctx[TSTEPS * BATCH * HID];
__device__ __align__(16) float g_sc[BATCH * SEQ * TPAD];   // [b][s][t]
__device__ float g_partial[TSTEPS];
__device__ unsigned g_barcnt = 0;
__device__ unsigned g_bargen = 0;

__device__ __forceinline__ float4 ld4(const float* p) {
    return *reinterpret_cast<const float4*>(p);
}
__device__ __forceinline__ ulonglong2 ld2u(const float* p) {
    return *reinterpret_cast<const ulonglong2*>(p);
}
__device__ __forceinline__ void ffma2(u64& d, u64 a, u64 b) {
    asm("fma.rn.f32x2 %0, %1, %2, %0;" : "+l"(d) : "l"(a), "l"(b));
}
__device__ __forceinline__ float upksum(u64 v) {
    float x, y;
    asm("mov.b64 {%0,%1}, %2;" : "=f"(x), "=f"(y) : "l"(v));
    return x + y;
}
__device__ __forceinline__ u32 smem_u32(const void* p) {
    u32 a;
    asm("{ .reg .u64 t; cvta.to.shared.u64 t, %1; cvt.u32.u64 %0, t; }" : "=r"(a) : "l"(p));
    return a;
}
__device__ __forceinline__ void grid_sync() {
    __syncthreads();
    if (threadIdx.x == 0) {
        volatile unsigned* vg = &g_bargen;
        unsigned gen = *vg;
        __threadfence();
        unsigned arr = atomicAdd(&g_barcnt, 1u);
        if (arr == gridDim.x - 1) {
            g_barcnt = 0u;
            __threadfence();
            atomicAdd(&g_bargen, 1u);
        } else {
            while (*vg == gen) { __nanosleep(32); }
        }
        __threadfence();
    }
    __syncthreads();
}
__device__ __forceinline__ void wreduce16(float a[16]) {
#pragma unroll
    for (int b = 0; b < 16; b++) {
#pragma unroll
        for (int off = 16; off; off >>= 1)
            a[b] += __shfl_xor_sync(0xffffffffu, a[b], off);
    }
}
__device__ __forceinline__ float pick16(const float a[16], int lane) {
    float r = 0.f;
#pragma unroll
    for (int b = 0; b < 16; b++) r = (lane == b) ? a[b] : r;
    return r;
}
__device__ __forceinline__ float red_gate(const u64* a, int lane) {
    float s[16];
#pragma unroll
    for (int b = 0; b < 16; b++) s[b] = upksum(a[b]);
    wreduce16(s);
    return pick16(s, lane);
}
__device__ __forceinline__ float sigmoidf_(float x) { return 1.f / (1.f + __expf(-x)); }
__device__ __forceinline__ float gate_h(float gi, float gf, float gG, float go, float& c) {
    float iv = sigmoidf_(gi), fv = sigmoidf_(gf);
    float gv = tanhf(gG), ov = sigmoidf_(go);
    c = fv * c + iv * gv;
    return ov * tanhf(c);
}

// ---------------- weight prepass (unchanged layout) ----------------
__global__ void __launch_bounds__(NTHR) prep_w(
    const float* __restrict__ Whh0,
    const float* __restrict__ Wih1, const float* __restrict__ Whh1,
    const float* __restrict__ Wih2, const float* __restrict__ Whh2) {
    for (u32 idx = blockIdx.x * NTHR + threadIdx.x; idx < WB_TOT; idx += gridDim.x * NTHR) {
        int l, Kh, steps; u32 base;
        if (idx < WB_B1)      { l = 0; Kh = 512;  steps = 32; base = WB_B0; }
        else if (idx < WB_B2) { l = 1; Kh = 1024; steps = 64; base = WB_B1; }
        else                  { l = 2; Kh = 1024; steps = 64; base = WB_B2; }
        u32 within = idx - base;
        int pc = 2 * steps * 128;
        int c = within / pc;   int r1 = within % pc;
        int h = r1 / (steps * 128); int r2 = r1 % (steps * 128);
        int s = r2 / 128;      int q  = r2 % 128;
        int lane = q >> 2;     int rr = (q >> 1) & 1; int e = q & 1;
        int k = h * Kh + s * 16 + (lane & 3) * 2 + 8 * rr + e;
        int n = lane >> 2;     int gate = n & 3;      int jl = n >> 2;
        int row = gate * 1024 + 2 * c + jl;
        float v;
        if (l == 0)      v = Whh0[(size_t)row * 1024 + k];
        else if (l == 1) v = (k < 1024) ? Wih1[(size_t)row * 1024 + k]
                                        : Whh1[(size_t)row * 1024 + k - 1024];
        else             v = (k < 1024) ? Wih2[(size_t)row * 1024 + k]
                                        : Whh2[(size_t)row * 1024 + k - 1024];
        g_Wb[idx] = __float2bfloat16(v);
    }
}

// ---------------- P0 (unchanged) ----------------
__global__ void __launch_bounds__(NTHR) p0_kernel(const float* __restrict__ emb,
                                                  const float* __restrict__ Wih0,
                                                  const float* __restrict__ bih0,
                                                  const float* __restrict__ bhh0) {
    __shared__ float se[16 * EMB];
    const int tid = threadIdx.x, lane = tid & 31, w = tid >> 5;
    const int v0 = blockIdx.x * 16;
    for (int i = tid; i < 16 * EMB; i += NTHR)
        se[i] = emb[(size_t)(v0 + (i >> 9)) * EMB + (i & 511)];
    __syncthreads();
    const int jbase = blockIdx.y * 1024;
    for (int j = jbase + w * 2; j < jbase + 1024; j += 16) {
        u64 aA[16], aB[16];
#pragma unroll
        for (int b = 0; b < 16; b++) { aA[b] = 0ull; aB[b] = 0ull; }
#pragma unroll
        for (int i = 0; i < EMB / 128; i++) {
            int k = 4 * lane + 128 * i;
            ulonglong2 wA = ld2u(Wih0 + (size_t)j * (EMB + ENC2D) + k);
            ulonglong2 wB = ld2u(Wih0 + (size_t)(j + 1) * (EMB + ENC2D) + k);
#pragma unroll
            for (int v = 0; v < 16; v++) {
                ulonglong2 e2 = ld2u(se + v * EMB + k);
                ffma2(aA[v], wA.x, e2.x); ffma2(aA[v], wA.y, e2.y);
                ffma2(aB[v], wB.x, e2.x); ffma2(aB[v], wB.y, e2.y);
            }
        }
        float vA = red_gate(aA, lane), vB = red_gate(aB, lane);
        if (lane < 16) {
            g_P0[(size_t)(v0 + lane) * G4 + j]     = vA + bih0[j]     + bhh0[j];
            g_P0[(size_t)(v0 + lane) * G4 + j + 1] = vB + bih0[j + 1] + bhh0[j + 1];
        }
    }
}

// ---------------- tensor-core recurrence ----------------
#define XSTRIDE 2064
#define XSZ     33024
#define PAIROFF 99072
#define W0OFF   103168
#define REC_SMEM 168704

// dual-accumulator mma loop, weights from global
template<int STEPS>
__device__ __forceinline__ void mma_loop(u32 addr, const __nv_bfloat16* wp, int lane,
                                         float& d0, float& d1, float& d2, float& d3) {
    float e0 = 0.f, e1 = 0.f, e2 = 0.f, e3 = 0.f;
    d0 = d1 = d2 = d3 = 0.f;
    const u64* wq = reinterpret_cast<const u64*>(wp + lane * 4);
#pragma unroll 4
    for (int s = 0; s < STEPS; s += 2) {
        u32 a0, a1, a2, a3;
        asm volatile("ldmatrix.sync.aligned.m8n8.x4.shared.b16 {%0,%1,%2,%3}, [%4];"
            : "=r"(a0), "=r"(a1), "=r"(a2), "=r"(a3) : "r"(addr));
        u64 bw = wq[s * 32];
        asm volatile("mma.sync.aligned.m16n8k16.row.col.f32.bf16.bf16.f32 "
            "{%0,%1,%2,%3}, {%4,%5,%6,%7}, {%8,%9}, {%0,%1,%2,%3};"
            : "+f"(d0), "+f"(d1), "+f"(d2), "+f"(d3)
            : "r"(a0), "r"(a1), "r"(a2), "r"(a3), "r"((u32)bw), "r"((u32)(bw >> 32)));
        u32 c0_, c1_, c2_, c3_;
        asm volatile("ldmatrix.sync.aligned.m8n8.x4.shared.b16 {%0,%1,%2,%3}, [%4];"
            : "=r"(c0_), "=r"(c1_), "=r"(c2_), "=r"(c3_) : "r"(addr + 32));
        u64 bw2 = wq[(s + 1) * 32];
        asm volatile("mma.sync.aligned.m16n8k16.row.col.f32.bf16.bf16.f32 "
            "{%0,%1,%2,%3}, {%4,%5,%6,%7}, {%8,%9}, {%0,%1,%2,%3};"
            : "+f"(e0), "+f"(e1), "+f"(e2), "+f"(e3)
            : "r"(c0_), "r"(c1_), "r"(c2_), "r"(c3_), "r"((u32)bw2), "r"((u32)(bw2 >> 32)));
        addr += 64;
    }
    d0 += e0; d1 += e1; d2 += e2; d3 += e3;
}

// dual-accumulator mma loop, weights from shared memory
template<int STEPS>
__device__ __forceinline__ void mma_loop_sw(u32 addr, u32 waddr,
                                            float& d0, float& d1, float& d2, float& d3) {
    float e0 = 0.f, e1 = 0.f, e2 = 0.f, e3 = 0.f;
    d0 = d1 = d2 = d3 = 0.f;
#pragma unroll 4
    for (int s = 0; s < STEPS; s += 2) {
        u32 a0, a1, a2, a3;
        asm volatile("ldmatrix.sync.aligned.m8n8.x4.shared.b16 {%0,%1,%2,%3}, [%4];"
            : "=r"(a0), "=r"(a1), "=r"(a2), "=r"(a3) : "r"(addr));
        u64 bw;
        asm volatile("ld.shared.b64 %0, [%1];" : "=l"(bw) : "r"(waddr + s * 256));
        asm volatile("mma.sync.aligned.m16n8k16.row.col.f32.bf16.bf16.f32 "
            "{%0,%1,%2,%3}, {%4,%5,%6,%7}, {%8,%9}, {%0,%1,%2,%3};"
            : "+f"(d0), "+f"(d1), "+f"(d2), "+f"(d3)
            : "r"(a0), "r"(a1), "r"(a2), "r"(a3), "r"((u32)bw), "r"((u32)(bw >> 32)));
        u32 c0_, c1_, c2_, c3_;
        asm volatile("ldmatrix.sync.aligned.m8n8.x4.shared.b16 {%0,%1,%2,%3}, [%4];"
            : "=r"(c0_), "=r"(c1_), "=r"(c2_), "=r"(c3_) : "r"(addr + 32));
        u64 bw2;
        asm volatile("ld.shared.b64 %0, [%1];" : "=l"(bw2) : "r"(waddr + (s + 1) * 256));
        asm volatile("mma.sync.aligned.m16n8k16.row.col.f32.bf16.bf16.f32 "
            "{%0,%1,%2,%3}, {%4,%5,%6,%7}, {%8,%9}, {%0,%1,%2,%3};"
            : "+f"(e0), "+f"(e1), "+f"(e2), "+f"(e3)
            : "r"(c0_), "r"(c1_), "r"(c2_), "r"(c3_), "r"((u32)bw2), "r"((u32)(bw2 >> 32)));
        addr += 64;
    }
    d0 += e0; d1 += e1; d2 += e2; d3 += e3;
}

__device__ __forceinline__ void combine(float* pp, float* gg, int half, int lane, int barid,
                                        float d0, float d1, float d2, float d3) {
    if (half) {
        ((float4*)pp)[lane] = make_float4(d0, d1, d2, d3);
        asm volatile("bar.sync %0, 64;" :: "r"(barid) : "memory");
    } else {
        asm volatile("bar.sync %0, 64;" :: "r"(barid) : "memory");
        float4 q = ((float4*)pp)[lane];
        d0 += q.x; d1 += q.y; d2 += q.z; d3 += q.w;
        int r = lane >> 2, cc = (lane & 3) * 2;
        gg[((cc    ) >> 2) * 64 + ((cc    ) & 3) * 16 + r    ] = d0;
        gg[((cc + 1) >> 2) * 64 + ((cc + 1) & 3) * 16 + r    ] = d1;
        gg[((cc    ) >> 2) * 64 + ((cc    ) & 3) * 16 + r + 8] = d2;
        gg[((cc + 1) >> 2) * 64 + ((cc + 1) & 3) * 16 + r + 8] = d3;
        __syncwarp();
    }
}

__global__ void __launch_bounds__(NTHR, 1) rec_kernel(
    const int* __restrict__ tokens,
    const float* __restrict__ bih1, const float* __restrict__ bhh1,
    const float* __restrict__ bih2, const float* __restrict__ bhh2) {
    extern __shared__ char smem[];
    const int tid = threadIdx.x, lane = tid & 31, w = tid >> 5;
    const int pairid = w >> 1, half = w & 1;
    const int chunk = blockIdx.x * 4 + pairid;
    const int j0 = chunk * 2;
    const int bL = lane & 15, jl = lane >> 4, jg = j0 + jl;
    const int barid = pairid + 1;

    u32 sb = smem_u32(smem);
    const int arow = lane & 15;
    const int acolb = ((lane >= 16) ? 8 : 0) * 2;
    u32 xa0 = sb + arow * XSTRIDE + acolb;
    u32 xa1 = xa0 + XSZ;
    u32 xa2 = xa1 + XSZ;
    float* pp = (float*)(smem + PAIROFF + pairid * 1024);
    float* gg = pp + 128;

    const __nv_bfloat16* w0 = g_Wb + WB_B0 + (size_t)(chunk * 2 + half) * 32 * 128;
    const __nv_bfloat16* w1 = g_Wb + WB_B1 + (size_t)(chunk * 2 + half) * 64 * 128;
    const __nv_bfloat16* w2 = g_Wb + WB_B2 + (size_t)(chunk * 2 + half) * 64 * 128;

    for (int i = tid; i < (3 * XSZ) / 4; i += NTHR) ((u32*)smem)[i] = 0u;
    // cache this warp's layer-0 weight stream (8 KB) in smem
    {
        const u64* srcw = (const u64*)w0;
        u64* dstw = (u64*)(smem + W0OFF + (size_t)w * 8192);
        for (int i = lane; i < 1024; i += 32) dstw[i] = srcw[i];
    }
    __syncthreads();
    const u32 w0addr = sb + W0OFF + w * 8192 + lane * 8;

    float B1g[4], B2g[4];
#pragma unroll
    for (int gt = 0; gt < 4; gt++) {
        B1g[gt] = bih1[gt * 1024 + jg] + bhh1[gt * 1024 + jg];
        B2g[gt] = bih2[gt * 1024 + jg] + bhh2[gt * 1024 + jg];
    }
    float c0 = 0.f, c1 = 0.f, c2 = 0.f;

    for (int tick = 0; tick < TSTEPS + 2; tick++) {
        // ---- layer 0 at t = tick ----
        if (tick <= 256) {
            // prefetch P0 gate values before the MMA
            float pvi = 0.f, pvf = 0.f, pvg = 0.f, pvo = 0.f;
            if (!half && lane < BATCH) {
                int tok = (tick == 0) ? SOS_TOK : tokens[bL * 256 + tick - 1];
                const float* p = g_P0 + (size_t)tok * G4 + jg;
                pvi = __ldg(p); pvf = __ldg(p + 1024);
                pvg = __ldg(p + 2048); pvo = __ldg(p + 3072);
            }
            float d0, d1, d2, d3;
            mma_loop_sw<32>(xa0 + (half ? 1024 : 0), w0addr, d0, d1, d2, d3);
            combine(pp, gg, half, lane, barid, d0, d1, d2, d3);
            if (!half && lane < BATCH) {
                float h = gate_h(gg[jl * 64 + bL] + pvi,
                                 gg[jl * 64 + 16 + bL] + pvf,
                                 gg[jl * 64 + 32 + bL] + pvg,
                                 gg[jl * 64 + 48 + bL] + pvo, c0);
                g_hb[0][bL * 1024 + jg] = __float2bfloat16(h);
            }
            asm volatile("bar.sync %0, 64;" :: "r"(barid) : "memory");
        }
        // ---- layer 1 at t = tick-1 ----
        if (tick >= 1 && tick <= 257) {
            float d0, d1, d2, d3;
            mma_loop<64>(half ? xa1 : xa0, w1, lane, d0, d1, d2, d3);
            combine(pp, gg, half, lane, barid, d0, d1, d2, d3);
            if (!half && lane < BATCH) {
                float h = gate_h(gg[jl * 64 + bL] + B1g[0],
                                 gg[jl * 64 + 16 + bL] + B1g[1],
                                 gg[jl * 64 + 32 + bL] + B1g[2],
                                 gg[jl * 64 + 48 + bL] + B1g[3], c1);
                g_hb[1][bL * 1024 + jg] = __float2bfloat16(h);
            }
            asm volatile("bar.sync %0, 64;" :: "r"(barid) : "memory");
        }
        // ---- layer 2 at t = tick-2 ----
        if (tick >= 2) {
            float d0, d1, d2, d3;
            mma_loop<64>(half ? xa2 : xa1, w2, lane, d0, d1, d2, d3);
            combine(pp, gg, half, lane, barid, d0, d1, d2, d3);
            if (!half && lane < BATCH) {
                float h = gate_h(gg[jl * 64 + bL] + B2g[0],
                                 gg[jl * 64 + 16 + bL] + B2g[1],
                                 gg[jl * 64 + 32 + bL] + B2g[2],
                                 gg[jl * 64 + 48 + bL] + B2g[3], c2);
                g_hb[2][bL * 1024 + jg] = __float2bfloat16(h);
                g_hs[(size_t)(tick - 2) * (BATCH * HID) + bL * 1024 + jg] = h;
            }
            asm volatile("bar.sync %0, 64;" :: "r"(barid) : "memory");
        }
        grid_sync();
        if (tick >= 2 && tick <= 256) {
            // steady state: fused triple reload (3 loads in flight per iter)
            const u64* p0h = (const u64*)g_hb[0];
            const u64* p1h = (const u64*)g_hb[1];
            const u64* p2h = (const u64*)g_hb[2];
            for (int i = tid; i < 2048; i += NTHR) {
                u64 v0 = __ldcg(p0h + i);
                u64 v1 = __ldcg(p1h + i);
                u64 v2 = __ldcg(p2h + i);
                u32 off = (i >> 8) * XSTRIDE + (i & 255) * 8;
                *(u64*)(smem + off) = v0;
                *(u64*)(smem + XSZ + off) = v1;
                *(u64*)(smem + 2 * XSZ + off) = v2;
            }
        } else {
            if (tick <= 256)
                for (int i = tid; i < 2048; i += NTHR) {
                    u64 v = __ldcg((const u64*)(g_hb[0]) + i);
                    *(u64*)(smem + (i >> 8) * XSTRIDE + (i & 255) * 8) = v;
                }
            if (tick >= 1 && tick <= 257)
                for (int i = tid; i < 2048; i += NTHR) {
                    u64 v = __ldcg((const u64*)(g_hb[1]) + i);
                    *(u64*)(smem + XSZ + (i >> 8) * XSTRIDE + (i & 255) * 8) = v;
                }
            if (tick >= 2 && tick <= 257)
                for (int i = tid; i < 2048; i += NTHR) {
                    u64 v = __ldcg((const u64*)(g_hb[2]) + i);
                    *(u64*)(smem + 2 * XSZ + (i >> 8) * XSTRIDE + (i & 255) * 8) = v;
                }
        }
        __syncthreads();
    }
}

// ---------------- attention: scores (s-split for occupancy) ----------------
__global__ void __launch_bounds__(NTHR, 2) scores_kernel(const float* __restrict__ enc) {
    extern __shared__ float sm[];
    float* sh_hs = sm;                 // [16][1024]
    const int tid = threadIdx.x, lane = tid & 31, w = tid >> 5;
    const int t0 = blockIdx.x * 16, b = blockIdx.y, sc = blockIdx.z;

    for (int i = tid; i < 16 * HID; i += NTHR) {
        int t = t0 + (i >> 10);
        sh_hs[i] = (t < TSTEPS) ? g_hs[(size_t)t * (BATCH * HID) + b * HID + (i & 1023)] : 0.f;
    }
    __syncthreads();
    const float* encb = enc + (size_t)b * SEQ * ENC2D;

    const int sbase = sc * 128;
    for (int s0 = sbase + w * 2; s0 < sbase + 128; s0 += 16) {
        u64 aA[16], aB[16];
#pragma unroll
        for (int i = 0; i < 16; i++) { aA[i] = 0ull; aB[i] = 0ull; }
        const float* e0 = encb + (size_t)s0 * ENC2D;
        const float* e1 = e0 + ENC2D;
#pragma unroll 2
        for (int i = 0; i < ENC2D / 128; i++) {
            int k = 4 * lane + 128 * i;
            ulonglong2 ea = ld2u(e0 + k), eb = ld2u(e1 + k);
#pragma unroll
            for (int tt = 0; tt < 16; tt++) {
                ulonglong2 h2 = ld2u(sh_hs + tt * HID + k);
                ffma2(aA[tt], ea.x, h2.x); ffma2(aA[tt], ea.y, h2.y);
                ffma2(aB[tt], eb.x, h2.x); ffma2(aB[tt], eb.y, h2.y);
            }
        }
        float vA = red_gate(aA, lane), vB = red_gate(aB, lane);
        if (lane < 16 && t0 + lane < TSTEPS) {
            g_sc[((size_t)b * SEQ + s0) * TPAD + t0 + lane] = vA;
            g_sc[((size_t)b * SEQ + s0 + 1) * TPAD + t0 + lane] = vB;
        }
    }
}

// ---------------- attention: softmax over s per (b, t) ----------------
__global__ void __launch_bounds__(128) soft_kernel() {
    const int bx = blockIdx.x;
    const int b = bx / TSTEPS, t = bx - b * TSTEPS;
    const int tid = threadIdx.x, lane = tid & 31, w = tid >> 5;
    __shared__ float red[8];
    float v[4];
    float mx = -1e30f;
#pragma unroll
    for (int q = 0; q < 4; q++) {
        int s = tid + q * 128;
        v[q] = g_sc[((size_t)b * SEQ + s) * TPAD + t];
        mx = fmaxf(mx, v[q]);
    }
#pragma unroll
    for (int o = 16; o; o >>= 1) mx = fmaxf(mx, __shfl_xor_sync(0xffffffffu, mx, o));
    if (lane == 0) red[w] = mx;
    __syncthreads();
    mx = fmaxf(fmaxf(red[0], red[1]), fmaxf(red[2], red[3]));
    float sum = 0.f;
#pragma unroll
    for (int q = 0; q < 4; q++) { v[q] = __expf(v[q] - mx); sum += v[q]; }
#pragma unroll
    for (int o = 16; o; o >>= 1) sum += __shfl_xor_sync(0xffffffffu, sum, o);
    if (lane == 0) red[4 + w] = sum;
    __syncthreads();
    sum = red[4] + red[5] + red[6] + red[7];
    float inv = 1.f / sum;
#pragma unroll
    for (int q = 0; q < 4; q++)
        g_sc[((size_t)b * SEQ + tid + q * 128) * TPAD + t] = v[q] * inv;
}

// ---------------- attention: ctx (k-split, tt-pair ffma2) ----------------
__global__ void __launch_bounds__(NTHR) ctx_kernel(const float* __restrict__ enc) {
    __shared__ __align__(16) float satt[SEQ * 16];   // 32 KB [s][tt]
    const int tid = threadIdx.x;
    const int t0 = blockIdx.x * 16, b = blockIdx.y, kc = blockIdx.z;

    for (int i = tid; i < SEQ * 16; i += NTHR) {
        int s = i >> 4, tt = i & 15;
        int t = t0 + tt;
        satt[i] = (t < TSTEPS) ? g_sc[((size_t)b * SEQ + s) * TPAD + t] : 0.f;
    }
    __syncthreads();

    const int k = kc * 256 + tid;
    const float* ek = enc + (size_t)b * SEQ * ENC2D + k;
    u64 acc[8];
#pragma unroll
    for (int p = 0; p < 8; p++) acc[p] = 0ull;
#pragma unroll 4
    for (int s = 0; s < SEQ; s++) {
        float ev = __ldg(ek + (size_t)s * ENC2D);
        u64 evv;
        asm("mov.b64 %0, {%1,%1};" : "=l"(evv) : "f"(ev));
        const ulonglong2* ap = (const ulonglong2*)(satt + s * 16);
        ulonglong2 q0 = ap[0], q1 = ap[1], q2 = ap[2], q3 = ap[3];
        ffma2(acc[0], evv, q0.x); ffma2(acc[1], evv, q0.y);
        ffma2(acc[2], evv, q1.x); ffma2(acc[3], evv, q1.y);
        ffma2(acc[4], evv, q2.x); ffma2(acc[5], evv, q2.y);
        ffma2(acc[6], evv, q3.x); ffma2(acc[7], evv, q3.y);
    }
#pragma unroll
    for (int p = 0; p < 8; p++) {
        float lo, hi;
        asm("mov.b64 {%0,%1}, %2;" : "=f"(lo), "=f"(hi) : "l"(acc[p]));
        int t = t0 + 2 * p;
        if (t < TSTEPS)     g_ctx[(size_t)t * (BATCH * HID) + b * HID + k] = lo;
        if (t + 1 < TSTEPS) g_ctx[(size_t)(t + 1) * (BATCH * HID) + b * HID + k] = hi;
    }
}

// ---------------- fused MLP + logits + NLL per t (unchanged) ----------------
__global__ void __launch_bounds__(NTHR, 1) mlp_kernel(
    const int* __restrict__ tokens,
    const float* __restrict__ W1, const float* __restrict__ b1,
    const float* __restrict__ W2, const float* __restrict__ b2) {
    extern __shared__ float sm[];
    float* sx = sm;
    float* sh = sm + 16 * 2048;
    float* red = sm + 16 * 2048 + 16 * 1024;
    const int tid = threadIdx.x, lane = tid & 31, w = tid >> 5;
    const int t = blockIdx.x;

    for (int i = tid; i < 16 * 1024; i += NTHR) {
        int b = i >> 10, k = i & 1023;
        sx[b * 2048 + k] = g_hs[(size_t)t * (BATCH * HID) + i];
        sx[b * 2048 + 1024 + k] = g_ctx[(size_t)t * (BATCH * HID) + i];
    }
    __syncthreads();

    for (int j0 = w * 4; j0 < 1024; j0 += 32) {
        u64 a0[16], a1[16], a2[16], a3[16];
#pragma unroll
        for (int b = 0; b < 16; b++) { a0[b] = a1[b] = a2[b] = a3[b] = 0ull; }
        const float* R0 = W1 + (size_t)j0 * 2048;
        const float* R1 = R0 + 2048;
        const float* R2 = R1 + 2048;
        const float* R3 = R2 + 2048;
#pragma unroll 2
        for (int i = 0; i < 2048 / 128; i++) {
            int k = 4 * lane + 128 * i;
            ulonglong2 w0 = ld2u(R0 + k), w1 = ld2u(R1 + k), w2 = ld2u(R2 + k), w3 = ld2u(R3 + k);
#pragma unroll
            for (int b = 0; b < 16; b++) {
                ulonglong2 x2 = ld2u(sx + b * 2048 + k);
                ffma2(a0[b], w0.x, x2.x); ffma2(a0[b], w0.y, x2.y);
                ffma2(a1[b], w1.x, x2.x); ffma2(a1[b], w1.y, x2.y);
                ffma2(a2[b], w2.x, x2.x); ffma2(a2[b], w2.y, x2.y);
                ffma2(a3[b], w3.x, x2.x); ffma2(a3[b], w3.y, x2.y);
            }
        }
        float v0 = red_gate(a0, lane), v1 = red_gate(a1, lane);
        float v2 = red_gate(a2, lane), v3 = red_gate(a3, lane);
        if (lane < 16) {
            sh[lane * 1024 + j0 + 0] = tanhf(v0 + b1[j0 + 0]);
            sh[lane * 1024 + j0 + 1] = tanhf(v1 + b1[j0 + 1]);
            sh[lane * 1024 + j0 + 2] = tanhf(v2 + b1[j0 + 2]);
            sh[lane * 1024 + j0 + 3] = tanhf(v3 + b1[j0 + 3]);
        }
    }
    __syncthreads();

    float M = -1e30f, S = 0.f, TV = 0.f;
    int tgt = 0;
    if (lane < 16) tgt = (t < 256) ? tokens[lane * 256 + t] : EOS_TOK;

    for (int j0 = w * 4; j0 < 1024; j0 += 32) {
        u64 a0[16], a1[16], a2[16], a3[16];
#pragma unroll
        for (int b = 0; b < 16; b++) { a0[b] = a1[b] = a2[b] = a3[b] = 0ull; }
        const float* R0 = W2 + (size_t)j0 * 1024;
        const float* R1 = R0 + 1024;
        const float* R2 = R1 + 1024;
        const float* R3 = R2 + 1024;
#pragma unroll 2
        for (int i = 0; i < 1024 / 128; i++) {
            int k = 4 * lane + 128 * i;
            ulonglong2 w0 = ld2u(R0 + k), w1 = ld2u(R1 + k), w2 = ld2u(R2 + k), w3 = ld2u(R3 + k);
#pragma unroll
            for (int b = 0; b < 16; b++) {
                ulonglong2 h2 = ld2u(sh + b * 1024 + k);
                ffma2(a0[b], w0.x, h2.x); ffma2(a0[b], w0.y, h2.y);
                ffma2(a1[b], w1.x, h2.x); ffma2(a1[b], w1.y, h2.y);
                ffma2(a2[b], w2.x, h2.x); ffma2(a2[b], w2.y, h2.y);
                ffma2(a3[b], w3.x, h2.x); ffma2(a3[b], w3.y, h2.y);
            }
        }
        float v[4];
        v[0] = red_gate(a0, lane); v[1] = red_gate(a1, lane);
        v[2] = red_gate(a2, lane); v[3] = red_gate(a3, lane);
        if (lane < 16) {
#pragma unroll
            for (int r = 0; r < 4; r++) {
                float val = v[r] + b2[j0 + r];
                float mn = fmaxf(M, val);
                S = S * __expf(M - mn) + __expf(val - mn);
                M = mn;
                if (j0 + r == tgt) TV = val;
            }
        }
    }
    if (lane < 16) {
        red[(w * 16 + lane) * 3 + 0] = M;
        red[(w * 16 + lane) * 3 + 1] = S;
        red[(w * 16 + lane) * 3 + 2] = TV;
    }
    __syncthreads();
    if (w == 0 && lane < 16) {
        float m = -1e30f, s = 0.f, tv = 0.f;
        for (int ww = 0; ww < 8; ww++) {
            float mw = red[(ww * 16 + lane) * 3 + 0];
            float sw = red[(ww * 16 + lane) * 3 + 1];
            tv += red[(ww * 16 + lane) * 3 + 2];
            float mn = fmaxf(m, mw);
            s = s * __expf(m - mn) + sw * __expf(mw - mn);
            m = mn;
        }
        float nll = (m + logf(s)) - tv;
#pragma unroll
        for (int o = 8; o; o >>= 1) nll += __shfl_xor_sync(0xffffu, nll, o);
        if (lane == 0) g_partial[t] = nll;
    }
}

__global__ void reduce_kernel(float* out) {
    __shared__ float s[256];
    int tid = threadIdx.x;
    float v = g_partial[tid];
    if (tid == 0) v += g_partial[256];
    s[tid] = v; __syncthreads();
    for (int o = 128; o; o >>= 1) { if (tid < o) s[tid] += s[tid + o]; __syncthreads(); }
    if (tid == 0) out[0] = s[0] / (float)(TSTEPS * BATCH);
}

extern "C" void kernel_launch(void* const* d_in, const int* in_sizes, int n_in,
                              void* d_out, int out_size) {
    const int*   tokens = (const int*)d_in[0];
    const float* enc    = (const float*)d_in[1];
    const float* emb    = (const float*)d_in[2];
    const float* Wih0   = (const float*)d_in[3];
    const float* Whh0   = (const float*)d_in[4];
    const float* bih0   = (const float*)d_in[5];
    const float* bhh0   = (const float*)d_in[6];
    const float* Wih1   = (const float*)d_in[7];
    const float* Whh1   = (const float*)d_in[8];
    const float* bih1   = (const float*)d_in[9];
    const float* bhh1   = (const float*)d_in[10];
    const float* Wih2   = (const float*)d_in[11];
    const float* Whh2   = (const float*)d_in[12];
    const float* bih2   = (const float*)d_in[13];
    const float* bhh2   = (const float*)d_in[14];
    const float* W1     = (const float*)d_in[15];
    const float* b1     = (const float*)d_in[16];
    const float* W2     = (const float*)d_in[17];
    const float* b2     = (const float*)d_in[18];
    float* out = (float*)d_out;

    const int SCORES_SMEM = BATCH * HID * 4;                         // 65536
    const int MLP_SMEM = (16 * 2048 + 16 * 1024 + 8 * 16 * 3) * 4;   // 198144
    cudaFuncSetAttribute(rec_kernel,    cudaFuncAttributeMaxDynamicSharedMemorySize, REC_SMEM);
    cudaFuncSetAttribute(scores_kernel, cudaFuncAttributeMaxDynamicSharedMemorySize, SCORES_SMEM);
    cudaFuncSetAttribute(mlp_kernel,    cudaFuncAttributeMaxDynamicSharedMemorySize, MLP_SMEM);

    prep_w<<<2048, NTHR>>>(Whh0, Wih1, Whh1, Wih2, Whh2);
    p0_kernel<<<dim3(64, 4), NTHR>>>(emb, Wih0, bih0, bhh0);
    rec_kernel<<<128, NTHR, REC_SMEM>>>(tokens, bih1, bhh1, bih2, bhh2);
    scores_kernel<<<dim3(17, 16, 4), NTHR, SCORES_SMEM>>>(enc);
    soft_kernel<<<16 * TSTEPS, 128>>>();
    ctx_kernel<<<dim3(17, 16, 4), NTHR>>>(enc);
    mlp_kernel<<<TSTEPS, NTHR, MLP_SMEM>>>(tokens, W1, b1, W2, b2);
    reduce_kernel<<<1, 256>>>(out);
}

// round 12
// speedup vs baseline: 1.2960x; 1.2960x over previous
#include <cuda_runtime.h>
#include <cuda_bf16.h>
#include <cstdint>
#include <math.h>

#define BATCH 16
#define HID   1024
#define G4    (4*HID)
#define TSTEPS 257
#define TPAD  272
#define VOC   1024
#define EMB   512
#define SEQ   512
#define ENC2D 1024
#define SOS_TOK 1
#define EOS_TOK 2
#define NTHR 256

typedef unsigned long long u64;
typedef unsigned int u32;

#define WB_B0 0u
#define WB_B1 4194304u
#define WB_B2 12582912u
#define WB_TOT 20971520u

// ---------------- device scratch ----------------
__device__ float g_P0[VOC * G4];
__device__ __align__(16) __nv_bfloat16 g_Wb[WB_TOT];
__device__ __align__(16) __nv_bfloat16 g_hb[3][BATCH * HID];
__device__ float g_hs[TSTEPS * BATCH * HID];
__device__ float g_ctx[TSTEPS * BATCH * HID];
__device__ __align__(16) float g_sc[BATCH * SEQ * TPAD];   // [b][s][t]
__device__ float g_partial[TSTEPS];
__device__ unsigned g_barcnt = 0;
__device__ unsigned g_bargen = 0;

__device__ __forceinline__ float4 ld4(const float* p) {
    return *reinterpret_cast<const float4*>(p);
}
__device__ __forceinline__ ulonglong2 ld2u(const float* p) {
    return *reinterpret_cast<const ulonglong2*>(p);
}
__device__ __forceinline__ void ffma2(u64& d, u64 a, u64 b) {
    asm("fma.rn.f32x2 %0, %1, %2, %0;" : "+l"(d) : "l"(a), "l"(b));
}
__device__ __forceinline__ float upksum(u64 v) {
    float x, y;
    asm("mov.b64 {%0,%1}, %2;" : "=f"(x), "=f"(y) : "l"(v));
    return x + y;
}
__device__ __forceinline__ u32 smem_u32(const void* p) {
    u32 a;
    asm("{ .reg .u64 t; cvta.to.shared.u64 t, %1; cvt.u32.u64 %0, t; }" : "=r"(a) : "l"(p));
    return a;
}
__device__ __forceinline__ void grid_sync() {
    __syncthreads();
    if (threadIdx.x == 0) {
        volatile unsigned* vg = &g_bargen;
        unsigned gen = *vg;
        __threadfence();
        unsigned arr = atomicAdd(&g_barcnt, 1u);
        if (arr == gridDim.x - 1) {
            g_barcnt = 0u;
            __threadfence();
            atomicAdd(&g_bargen, 1u);
        } else {
            while (*vg == gen) { __nanosleep(32); }
        }
        __threadfence();
    }
    __syncthreads();
}
__device__ __forceinline__ void wreduce16(float a[16]) {
#pragma unroll
    for (int b = 0; b < 16; b++) {
#pragma unroll
        for (int off = 16; off; off >>= 1)
            a[b] += __shfl_xor_sync(0xffffffffu, a[b], off);
    }
}
__device__ __forceinline__ float pick16(const float a[16], int lane) {
    float r = 0.f;
#pragma unroll
    for (int b = 0; b < 16; b++) r = (lane == b) ? a[b] : r;
    return r;
}
__device__ __forceinline__ float red_gate(const u64* a, int lane) {
    float s[16];
#pragma unroll
    for (int b = 0; b < 16; b++) s[b] = upksum(a[b]);
    wreduce16(s);
    return pick16(s, lane);
}
__device__ __forceinline__ float sigmoidf_(float x) { return 1.f / (1.f + __expf(-x)); }
__device__ __forceinline__ float gate_h(float gi, float gf, float gG, float go, float& c) {
    float iv = sigmoidf_(gi), fv = sigmoidf_(gf);
    float gv = tanhf(gG), ov = sigmoidf_(go);
    c = fv * c + iv * gv;
    return ov * tanhf(c);
}

// ---------------- weight prepass ----------------
__global__ void __launch_bounds__(NTHR) prep_w(
    const float* __restrict__ Whh0,
    const float* __restrict__ Wih1, const float* __restrict__ Whh1,
    const float* __restrict__ Wih2, const float* __restrict__ Whh2) {
    for (u32 idx = blockIdx.x * NTHR + threadIdx.x; idx < WB_TOT; idx += gridDim.x * NTHR) {
        int l, Kh, steps; u32 base;
        if (idx < WB_B1)      { l = 0; Kh = 512;  steps = 32; base = WB_B0; }
        else if (idx < WB_B2) { l = 1; Kh = 1024; steps = 64; base = WB_B1; }
        else                  { l = 2; Kh = 1024; steps = 64; base = WB_B2; }
        u32 within = idx - base;
        int pc = 2 * steps * 128;
        int c = within / pc;   int r1 = within % pc;
        int h = r1 / (steps * 128); int r2 = r1 % (steps * 128);
        int s = r2 / 128;      int q  = r2 % 128;
        int lane = q >> 2;     int rr = (q >> 1) & 1; int e = q & 1;
        int k = h * Kh + s * 16 + (lane & 3) * 2 + 8 * rr + e;
        int n = lane >> 2;     int gate = n & 3;      int jl = n >> 2;
        int row = gate * 1024 + 2 * c + jl;
        float v;
        if (l == 0)      v = Whh0[(size_t)row * 1024 + k];
        else if (l == 1) v = (k < 1024) ? Wih1[(size_t)row * 1024 + k]
                                        : Whh1[(size_t)row * 1024 + k - 1024];
        else             v = (k < 1024) ? Wih2[(size_t)row * 1024 + k]
                                        : Whh2[(size_t)row * 1024 + k - 1024];
        g_Wb[idx] = __float2bfloat16(v);
    }
}

// ---------------- P0 ----------------
__global__ void __launch_bounds__(NTHR) p0_kernel(const float* __restrict__ emb,
                                                  const float* __restrict__ Wih0,
                                                  const float* __restrict__ bih0,
                                                  const float* __restrict__ bhh0) {
    __shared__ float se[16 * EMB];
    const int tid = threadIdx.x, lane = tid & 31, w = tid >> 5;
    const int v0 = blockIdx.x * 16;
    for (int i = tid; i < 16 * EMB; i += NTHR)
        se[i] = emb[(size_t)(v0 + (i >> 9)) * EMB + (i & 511)];
    __syncthreads();
    const int jbase = blockIdx.y * 1024;
    for (int j = jbase + w * 2; j < jbase + 1024; j += 16) {
        u64 aA[16], aB[16];
#pragma unroll
        for (int b = 0; b < 16; b++) { aA[b] = 0ull; aB[b] = 0ull; }
#pragma unroll
        for (int i = 0; i < EMB / 128; i++) {
            int k = 4 * lane + 128 * i;
            ulonglong2 wA = ld2u(Wih0 + (size_t)j * (EMB + ENC2D) + k);
            ulonglong2 wB = ld2u(Wih0 + (size_t)(j + 1) * (EMB + ENC2D) + k);
#pragma unroll
            for (int v = 0; v < 16; v++) {
                ulonglong2 e2 = ld2u(se + v * EMB + k);
                ffma2(aA[v], wA.x, e2.x); ffma2(aA[v], wA.y, e2.y);
                ffma2(aB[v], wB.x, e2.x); ffma2(aB[v], wB.y, e2.y);
            }
        }
        float vA = red_gate(aA, lane), vB = red_gate(aB, lane);
        if (lane < 16) {
            g_P0[(size_t)(v0 + lane) * G4 + j]     = vA + bih0[j]     + bhh0[j];
            g_P0[(size_t)(v0 + lane) * G4 + j + 1] = vB + bih0[j + 1] + bhh0[j + 1];
        }
    }
}

// ---------------- tensor-core recurrence (round-7 proven version) ----------------
#define XSTRIDE 2064
#define XSZ     33024
#define PAIROFF 99072
#define REC_SMEM 103168

template<int STEPS>
__device__ __forceinline__ void mma_loop(u32 addr, const __nv_bfloat16* wp, int lane,
                                         float& d0, float& d1, float& d2, float& d3) {
    d0 = d1 = d2 = d3 = 0.f;
    const u64* wq = reinterpret_cast<const u64*>(wp + lane * 4);
#pragma unroll 8
    for (int s = 0; s < STEPS; s++) {
        u32 a0, a1, a2, a3;
        asm volatile("ldmatrix.sync.aligned.m8n8.x4.shared.b16 {%0,%1,%2,%3}, [%4];"
            : "=r"(a0), "=r"(a1), "=r"(a2), "=r"(a3) : "r"(addr));
        u64 bw = wq[s * 32];
        u32 b0 = (u32)bw, b1 = (u32)(bw >> 32);
        asm volatile("mma.sync.aligned.m16n8k16.row.col.f32.bf16.bf16.f32 "
            "{%0,%1,%2,%3}, {%4,%5,%6,%7}, {%8,%9}, {%0,%1,%2,%3};"
            : "+f"(d0), "+f"(d1), "+f"(d2), "+f"(d3)
            : "r"(a0), "r"(a1), "r"(a2), "r"(a3), "r"(b0), "r"(b1));
        addr += 32;
    }
}

__device__ __forceinline__ void combine(float* pp, float* gg, int half, int lane, int barid,
                                        float d0, float d1, float d2, float d3) {
    if (half) {
        ((float4*)pp)[lane] = make_float4(d0, d1, d2, d3);
        asm volatile("bar.sync %0, 64;" :: "r"(barid) : "memory");
    } else {
        asm volatile("bar.sync %0, 64;" :: "r"(barid) : "memory");
        float4 q = ((float4*)pp)[lane];
        d0 += q.x; d1 += q.y; d2 += q.z; d3 += q.w;
        int r = lane >> 2, cc = (lane & 3) * 2;
        gg[((cc    ) >> 2) * 64 + ((cc    ) & 3) * 16 + r    ] = d0;
        gg[((cc + 1) >> 2) * 64 + ((cc + 1) & 3) * 16 + r    ] = d1;
        gg[((cc    ) >> 2) * 64 + ((cc    ) & 3) * 16 + r + 8] = d2;
        gg[((cc + 1) >> 2) * 64 + ((cc + 1) & 3) * 16 + r + 8] = d3;
        __syncwarp();
    }
}

__global__ void __launch_bounds__(NTHR, 1) rec_kernel(
    const int* __restrict__ tokens,
    const float* __restrict__ bih1, const float* __restrict__ bhh1,
    const float* __restrict__ bih2, const float* __restrict__ bhh2) {
    extern __shared__ char smem[];
    const int tid = threadIdx.x, lane = tid & 31, w = tid >> 5;
    const int pairid = w >> 1, half = w & 1;
    const int chunk = blockIdx.x * 4 + pairid;
    const int j0 = chunk * 2;
    const int bL = lane & 15, jl = lane >> 4, jg = j0 + jl;
    const int barid = pairid + 1;

    u32 sb = smem_u32(smem);
    const int arow = lane & 15;
    const int acolb = ((lane >= 16) ? 8 : 0) * 2;
    u32 xa0 = sb + arow * XSTRIDE + acolb;
    u32 xa1 = xa0 + XSZ;
    u32 xa2 = xa1 + XSZ;
    float* pp = (float*)(smem + PAIROFF + pairid * 1024);
    float* gg = pp + 128;

    for (int i = tid; i < (3 * XSZ) / 4; i += NTHR) ((u32*)smem)[i] = 0u;
    __syncthreads();

    const __nv_bfloat16* w0 = g_Wb + WB_B0 + (size_t)(chunk * 2 + half) * 32 * 128;
    const __nv_bfloat16* w1 = g_Wb + WB_B1 + (size_t)(chunk * 2 + half) * 64 * 128;
    const __nv_bfloat16* w2 = g_Wb + WB_B2 + (size_t)(chunk * 2 + half) * 64 * 128;

    float B1g[4], B2g[4];
#pragma unroll
    for (int gt = 0; gt < 4; gt++) {
        B1g[gt] = bih1[gt * 1024 + jg] + bhh1[gt * 1024 + jg];
        B2g[gt] = bih2[gt * 1024 + jg] + bhh2[gt * 1024 + jg];
    }
    float c0 = 0.f, c1 = 0.f, c2 = 0.f;

    for (int tick = 0; tick < TSTEPS + 2; tick++) {
        // ---- layer 0 at t = tick ----
        if (tick <= 256) {
            float d0, d1, d2, d3;
            mma_loop<32>(xa0 + (half ? 1024 : 0), w0, lane, d0, d1, d2, d3);
            combine(pp, gg, half, lane, barid, d0, d1, d2, d3);
            if (!half) {
                int tok = (tick == 0) ? SOS_TOK : tokens[bL * 256 + tick - 1];
                const float* p = g_P0 + (size_t)tok * G4 + jg;
                float h = gate_h(gg[jl * 64 + bL] + p[0],
                                 gg[jl * 64 + 16 + bL] + p[1024],
                                 gg[jl * 64 + 32 + bL] + p[2048],
                                 gg[jl * 64 + 48 + bL] + p[3072], c0);
                g_hb[0][bL * 1024 + jg] = __float2bfloat16(h);
            }
            asm volatile("bar.sync %0, 64;" :: "r"(barid) : "memory");
        }
        // ---- layer 1 at t = tick-1 ----
        if (tick >= 1 && tick <= 257) {
            float d0, d1, d2, d3;
            mma_loop<64>(half ? xa1 : xa0, w1, lane, d0, d1, d2, d3);
            combine(pp, gg, half, lane, barid, d0, d1, d2, d3);
            if (!half) {
                float h = gate_h(gg[jl * 64 + bL] + B1g[0],
                                 gg[jl * 64 + 16 + bL] + B1g[1],
                                 gg[jl * 64 + 32 + bL] + B1g[2],
                                 gg[jl * 64 + 48 + bL] + B1g[3], c1);
                g_hb[1][bL * 1024 + jg] = __float2bfloat16(h);
            }
            asm volatile("bar.sync %0, 64;" :: "r"(barid) : "memory");
        }
        // ---- layer 2 at t = tick-2 ----
        if (tick >= 2) {
            float d0, d1, d2, d3;
            mma_loop<64>(half ? xa2 : xa1, w2, lane, d0, d1, d2, d3);
            combine(pp, gg, half, lane, barid, d0, d1, d2, d3);
            if (!half) {
                float h = gate_h(gg[jl * 64 + bL] + B2g[0],
                                 gg[jl * 64 + 16 + bL] + B2g[1],
                                 gg[jl * 64 + 32 + bL] + B2g[2],
                                 gg[jl * 64 + 48 + bL] + B2g[3], c2);
                g_hb[2][bL * 1024 + jg] = __float2bfloat16(h);
                g_hs[(size_t)(tick - 2) * (BATCH * HID) + bL * 1024 + jg] = h;
            }
            asm volatile("bar.sync %0, 64;" :: "r"(barid) : "memory");
        }
        grid_sync();
        if (tick <= 256)
            for (int i = tid; i < 2048; i += NTHR) {
                u64 v = __ldcg((const u64*)(g_hb[0]) + i);
                *(u64*)(smem + (i >> 8) * XSTRIDE + (i & 255) * 8) = v;
            }
        if (tick >= 1 && tick <= 257)
            for (int i = tid; i < 2048; i += NTHR) {
                u64 v = __ldcg((const u64*)(g_hb[1]) + i);
                *(u64*)(smem + XSZ + (i >> 8) * XSTRIDE + (i & 255) * 8) = v;
            }
        if (tick >= 2 && tick <= 257)
            for (int i = tid; i < 2048; i += NTHR) {
                u64 v = __ldcg((const u64*)(g_hb[2]) + i);
                *(u64*)(smem + 2 * XSZ + (i >> 8) * XSTRIDE + (i & 255) * 8) = v;
            }
        __syncthreads();
    }
}

// ---------------- attention: scores ----------------
__global__ void __launch_bounds__(NTHR, 2) scores_kernel(const float* __restrict__ enc) {
    extern __shared__ float sm[];
    float* sh_hs = sm;                 // [16][1024]
    const int tid = threadIdx.x, lane = tid & 31, w = tid >> 5;
    const int t0 = blockIdx.x * 16, b = blockIdx.y, sc = blockIdx.z;

    for (int i = tid; i < 16 * HID; i += NTHR) {
        int t = t0 + (i >> 10);
        sh_hs[i] = (t < TSTEPS) ? g_hs[(size_t)t * (BATCH * HID) + b * HID + (i & 1023)] : 0.f;
    }
    __syncthreads();
    const float* encb = enc + (size_t)b * SEQ * ENC2D;

    const int sbase = sc * 128;
    for (int s0 = sbase + w * 2; s0 < sbase + 128; s0 += 16) {
        u64 aA[16], aB[16];
#pragma unroll
        for (int i = 0; i < 16; i++) { aA[i] = 0ull; aB[i] = 0ull; }
        const float* e0 = encb + (size_t)s0 * ENC2D;
        const float* e1 = e0 + ENC2D;
#pragma unroll 2
        for (int i = 0; i < ENC2D / 128; i++) {
            int k = 4 * lane + 128 * i;
            ulonglong2 ea = ld2u(e0 + k), eb = ld2u(e1 + k);
#pragma unroll
            for (int tt = 0; tt < 16; tt++) {
                ulonglong2 h2 = ld2u(sh_hs + tt * HID + k);
                ffma2(aA[tt], ea.x, h2.x); ffma2(aA[tt], ea.y, h2.y);
                ffma2(aB[tt], eb.x, h2.x); ffma2(aB[tt], eb.y, h2.y);
            }
        }
        float vA = red_gate(aA, lane), vB = red_gate(aB, lane);
        if (lane < 16 && t0 + lane < TSTEPS) {
            g_sc[((size_t)b * SEQ + s0) * TPAD + t0 + lane] = vA;
            g_sc[((size_t)b * SEQ + s0 + 1) * TPAD + t0 + lane] = vB;
        }
    }
}

// ---------------- attention: softmax ----------------
__global__ void __launch_bounds__(128) soft_kernel() {
    const int bx = blockIdx.x;
    const int b = bx / TSTEPS, t = bx - b * TSTEPS;
    const int tid = threadIdx.x, lane = tid & 31, w = tid >> 5;
    __shared__ float red[8];
    float v[4];
    float mx = -1e30f;
#pragma unroll
    for (int q = 0; q < 4; q++) {
        int s = tid + q * 128;
        v[q] = g_sc[((size_t)b * SEQ + s) * TPAD + t];
        mx = fmaxf(mx, v[q]);
    }
#pragma unroll
    for (int o = 16; o; o >>= 1) mx = fmaxf(mx, __shfl_xor_sync(0xffffffffu, mx, o));
    if (lane == 0) red[w] = mx;
    __syncthreads();
    mx = fmaxf(fmaxf(red[0], red[1]), fmaxf(red[2], red[3]));
    float sum = 0.f;
#pragma unroll
    for (int q = 0; q < 4; q++) { v[q] = __expf(v[q] - mx); sum += v[q]; }
#pragma unroll
    for (int o = 16; o; o >>= 1) sum += __shfl_xor_sync(0xffffffffu, sum, o);
    if (lane == 0) red[4 + w] = sum;
    __syncthreads();
    sum = red[4] + red[5] + red[6] + red[7];
    float inv = 1.f / sum;
#pragma unroll
    for (int q = 0; q < 4; q++)
        g_sc[((size_t)b * SEQ + tid + q * 128) * TPAD + t] = v[q] * inv;
}

// ---------------- attention: ctx ----------------
__global__ void __launch_bounds__(NTHR) ctx_kernel(const float* __restrict__ enc) {
    __shared__ __align__(16) float satt[SEQ * 16];   // 32 KB [s][tt]
    const int tid = threadIdx.x;
    const int t0 = blockIdx.x * 16, b = blockIdx.y, kc = blockIdx.z;

    for (int i = tid; i < SEQ * 16; i += NTHR) {
        int s = i >> 4, tt = i & 15;
        int t = t0 + tt;
        satt[i] = (t < TSTEPS) ? g_sc[((size_t)b * SEQ + s) * TPAD + t] : 0.f;
    }
    __syncthreads();

    const int k = kc * 256 + tid;
    const float* ek = enc + (size_t)b * SEQ * ENC2D + k;
    u64 acc[8];
#pragma unroll
    for (int p = 0; p < 8; p++) acc[p] = 0ull;
#pragma unroll 4
    for (int s = 0; s < SEQ; s++) {
        float ev = __ldg(ek + (size_t)s * ENC2D);
        u64 evv;
        asm("mov.b64 %0, {%1,%1};" : "=l"(evv) : "f"(ev));
        const ulonglong2* ap = (const ulonglong2*)(satt + s * 16);
        ulonglong2 q0 = ap[0], q1 = ap[1], q2 = ap[2], q3 = ap[3];
        ffma2(acc[0], evv, q0.x); ffma2(acc[1], evv, q0.y);
        ffma2(acc[2], evv, q1.x); ffma2(acc[3], evv, q1.y);
        ffma2(acc[4], evv, q2.x); ffma2(acc[5], evv, q2.y);
        ffma2(acc[6], evv, q3.x); ffma2(acc[7], evv, q3.y);
    }
#pragma unroll
    for (int p = 0; p < 8; p++) {
        float lo, hi;
        asm("mov.b64 {%0,%1}, %2;" : "=f"(lo), "=f"(hi) : "l"(acc[p]));
        int t = t0 + 2 * p;
        if (t < TSTEPS)     g_ctx[(size_t)t * (BATCH * HID) + b * HID + k] = lo;
        if (t + 1 < TSTEPS) g_ctx[(size_t)(t + 1) * (BATCH * HID) + b * HID + k] = hi;
    }
}

// ---------------- fused MLP + logits + NLL per t ----------------
__global__ void __launch_bounds__(NTHR, 1) mlp_kernel(
    const int* __restrict__ tokens,
    const float* __restrict__ W1, const float* __restrict__ b1,
    const float* __restrict__ W2, const float* __restrict__ b2) {
    extern __shared__ float sm[];
    float* sx = sm;
    float* sh = sm + 16 * 2048;
    float* red = sm + 16 * 2048 + 16 * 1024;
    const int tid = threadIdx.x, lane = tid & 31, w = tid >> 5;
    const int t = blockIdx.x;

    for (int i = tid; i < 16 * 1024; i += NTHR) {
        int b = i >> 10, k = i & 1023;
        sx[b * 2048 + k] = g_hs[(size_t)t * (BATCH * HID) + i];
        sx[b * 2048 + 1024 + k] = g_ctx[(size_t)t * (BATCH * HID) + i];
    }
    __syncthreads();

    for (int j0 = w * 4; j0 < 1024; j0 += 32) {
        u64 a0[16], a1[16], a2[16], a3[16];
#pragma unroll
        for (int b = 0; b < 16; b++) { a0[b] = a1[b] = a2[b] = a3[b] = 0ull; }
        const float* R0 = W1 + (size_t)j0 * 2048;
        const float* R1 = R0 + 2048;
        const float* R2 = R1 + 2048;
        const float* R3 = R2 + 2048;
#pragma unroll 2
        for (int i = 0; i < 2048 / 128; i++) {
            int k = 4 * lane + 128 * i;
            ulonglong2 w0 = ld2u(R0 + k), w1 = ld2u(R1 + k), w2 = ld2u(R2 + k), w3 = ld2u(R3 + k);
#pragma unroll
            for (int b = 0; b < 16; b++) {
                ulonglong2 x2 = ld2u(sx + b * 2048 + k);
                ffma2(a0[b], w0.x, x2.x); ffma2(a0[b], w0.y, x2.y);
                ffma2(a1[b], w1.x, x2.x); ffma2(a1[b], w1.y, x2.y);
                ffma2(a2[b], w2.x, x2.x); ffma2(a2[b], w2.y, x2.y);
                ffma2(a3[b], w3.x, x2.x); ffma2(a3[b], w3.y, x2.y);
            }
        }
        float v0 = red_gate(a0, lane), v1 = red_gate(a1, lane);
        float v2 = red_gate(a2, lane), v3 = red_gate(a3, lane);
        if (lane < 16) {
            sh[lane * 1024 + j0 + 0] = tanhf(v0 + b1[j0 + 0]);
            sh[lane * 1024 + j0 + 1] = tanhf(v1 + b1[j0 + 1]);
            sh[lane * 1024 + j0 + 2] = tanhf(v2 + b1[j0 + 2]);
            sh[lane * 1024 + j0 + 3] = tanhf(v3 + b1[j0 + 3]);
        }
    }
    __syncthreads();

    float M = -1e30f, S = 0.f, TV = 0.f;
    int tgt = 0;
    if (lane < 16) tgt = (t < 256) ? tokens[lane * 256 + t] : EOS_TOK;

    for (int j0 = w * 4; j0 < 1024; j0 += 32) {
        u64 a0[16], a1[16], a2[16], a3[16];
#pragma unroll
        for (int b = 0; b < 16; b++) { a0[b] = a1[b] = a2[b] = a3[b] = 0ull; }
        const float* R0 = W2 + (size_t)j0 * 1024;
        const float* R1 = R0 + 1024;
        const float* R2 = R1 + 1024;
        const float* R3 = R2 + 1024;
#pragma unroll 2
        for (int i = 0; i < 1024 / 128; i++) {
            int k = 4 * lane + 128 * i;
            ulonglong2 w0 = ld2u(R0 + k), w1 = ld2u(R1 + k), w2 = ld2u(R2 + k), w3 = ld2u(R3 + k);
#pragma unroll
            for (int b = 0; b < 16; b++) {
                ulonglong2 h2 = ld2u(sh + b * 1024 + k);
                ffma2(a0[b], w0.x, h2.x); ffma2(a0[b], w0.y, h2.y);
                ffma2(a1[b], w1.x, h2.x); ffma2(a1[b], w1.y, h2.y);
                ffma2(a2[b], w2.x, h2.x); ffma2(a2[b], w2.y, h2.y);
                ffma2(a3[b], w3.x, h2.x); ffma2(a3[b], w3.y, h2.y);
            }
        }
        float v[4];
        v[0] = red_gate(a0, lane); v[1] = red_gate(a1, lane);
        v[2] = red_gate(a2, lane); v[3] = red_gate(a3, lane);
        if (lane < 16) {
#pragma unroll
            for (int r = 0; r < 4; r++) {
                float val = v[r] + b2[j0 + r];
                float mn = fmaxf(M, val);
                S = S * __expf(M - mn) + __expf(val - mn);
                M = mn;
                if (j0 + r == tgt) TV = val;
            }
        }
    }
    if (lane < 16) {
        red[(w * 16 + lane) * 3 + 0] = M;
        red[(w * 16 + lane) * 3 + 1] = S;
        red[(w * 16 + lane) * 3 + 2] = TV;
    }
    __syncthreads();
    if (w == 0 && lane < 16) {
        float m = -1e30f, s = 0.f, tv = 0.f;
        for (int ww = 0; ww < 8; ww++) {
            float mw = red[(ww * 16 + lane) * 3 + 0];
            float sw = red[(ww * 16 + lane) * 3 + 1];
            tv += red[(ww * 16 + lane) * 3 + 2];
            float mn = fmaxf(m, mw);
            s = s * __expf(m - mn) + sw * __expf(mw - mn);
            m = mn;
        }
        float nll = (m + logf(s)) - tv;
#pragma unroll
        for (int o = 8; o; o >>= 1) nll += __shfl_xor_sync(0xffffu, nll, o);
        if (lane == 0) g_partial[t] = nll;
    }
}

__global__ void reduce_kernel(float* out) {
    __shared__ float s[256];
    int tid = threadIdx.x;
    float v = g_partial[tid];
    if (tid == 0) v += g_partial[256];
    s[tid] = v; __syncthreads();
    for (int o = 128; o; o >>= 1) { if (tid < o) s[tid] += s[tid + o]; __syncthreads(); }
    if (tid == 0) out[0] = s[0] / (float)(TSTEPS * BATCH);
}

extern "C" void kernel_launch(void* const* d_in, const int* in_sizes, int n_in,
                              void* d_out, int out_size) {
    const int*   tokens = (const int*)d_in[0];
    const float* enc    = (const float*)d_in[1];
    const float* emb    = (const float*)d_in[2];
    const float* Wih0   = (const float*)d_in[3];
    const float* Whh0   = (const float*)d_in[4];
    const float* bih0   = (const float*)d_in[5];
    const float* bhh0   = (const float*)d_in[6];
    const float* Wih1   = (const float*)d_in[7];
    const float* Whh1   = (const float*)d_in[8];
    const float* bih1   = (const float*)d_in[9];
    const float* bhh1   = (const float*)d_in[10];
    const float* Wih2   = (const float*)d_in[11];
    const float* Whh2   = (const float*)d_in[12];
    const float* bih2   = (const float*)d_in[13];
    const float* bhh2   = (const float*)d_in[14];
    const float* W1     = (const float*)d_in[15];
    const float* b1     = (const float*)d_in[16];
    const float* W2     = (const float*)d_in[17];
    const float* b2     = (const float*)d_in[18];
    float* out = (float*)d_out;

    const int SCORES_SMEM = BATCH * HID * 4;                         // 65536
    const int MLP_SMEM = (16 * 2048 + 16 * 1024 + 8 * 16 * 3) * 4;   // 198144
    cudaFuncSetAttribute(rec_kernel,    cudaFuncAttributeMaxDynamicSharedMemorySize, REC_SMEM);
    cudaFuncSetAttribute(scores_kernel, cudaFuncAttributeMaxDynamicSharedMemorySize, SCORES_SMEM);
    cudaFuncSetAttribute(mlp_kernel,    cudaFuncAttributeMaxDynamicSharedMemorySize, MLP_SMEM);

    prep_w<<<2048, NTHR>>>(Whh0, Wih1, Whh1, Wih2, Whh2);
    p0_kernel<<<dim3(64, 4), NTHR>>>(emb, Wih0, bih0, bhh0);
    rec_kernel<<<128, NTHR, REC_SMEM>>>(tokens, bih1, bhh1, bih2, bhh2);
    scores_kernel<<<dim3(17, 16, 4), NTHR, SCORES_SMEM>>>(enc);
    soft_kernel<<<16 * TSTEPS, 128>>>();
    ctx_kernel<<<dim3(17, 16, 4), NTHR>>>(enc);
    mlp_kernel<<<TSTEPS, NTHR, MLP_SMEM>>>(tokens, W1, b1, W2, b2);
    reduce_kernel<<<1, 256>>>(out);
}

// round 13
// speedup vs baseline: 1.4151x; 1.0919x over previous
#include <cuda_runtime.h>
#include <cuda_bf16.h>
#include <cstdint>
#include <math.h>

#define BATCH 16
#define HID   1024
#define G4    (4*HID)
#define TSTEPS 257
#define TPAD  272
#define VOC   1024
#define EMB   512
#define SEQ   512
#define ENC2D 1024
#define SOS_TOK 1
#define EOS_TOK 2
#define NTHR 256
#define RTHR 640

typedef unsigned long long u64;
typedef unsigned int u32;

#define WB_B0 0u
#define WB_B1 4194304u
#define WB_B2 12582912u
#define WB_TOT 20971520u

// ---------------- device scratch ----------------
__device__ float g_P0[VOC * G4];
__device__ __align__(16) __nv_bfloat16 g_Wb[WB_TOT];
__device__ __align__(16) __nv_bfloat16 g_hb[3][BATCH * HID];
__device__ float g_hs[TSTEPS * BATCH * HID];
__device__ float g_ctx[TSTEPS * BATCH * HID];
__device__ __align__(16) float g_sc[BATCH * SEQ * TPAD];   // [b][s][t]
__device__ float g_partial[TSTEPS];
__device__ unsigned g_barcnt = 0;
__device__ unsigned g_bargen = 0;

__device__ __forceinline__ float4 ld4(const float* p) {
    return *reinterpret_cast<const float4*>(p);
}
__device__ __forceinline__ ulonglong2 ld2u(const float* p) {
    return *reinterpret_cast<const ulonglong2*>(p);
}
__device__ __forceinline__ void ffma2(u64& d, u64 a, u64 b) {
    asm("fma.rn.f32x2 %0, %1, %2, %0;" : "+l"(d) : "l"(a), "l"(b));
}
__device__ __forceinline__ float upksum(u64 v) {
    float x, y;
    asm("mov.b64 {%0,%1}, %2;" : "=f"(x), "=f"(y) : "l"(v));
    return x + y;
}
__device__ __forceinline__ u32 smem_u32(const void* p) {
    u32 a;
    asm("{ .reg .u64 t; cvta.to.shared.u64 t, %1; cvt.u32.u64 %0, t; }" : "=r"(a) : "l"(p));
    return a;
}
__device__ __forceinline__ void grid_sync() {
    __syncthreads();
    if (threadIdx.x == 0) {
        volatile unsigned* vg = &g_bargen;
        unsigned gen = *vg;
        __threadfence();
        unsigned arr = atomicAdd(&g_barcnt, 1u);
        if (arr == gridDim.x - 1) {
            g_barcnt = 0u;
            __threadfence();
            atomicAdd(&g_bargen, 1u);
        } else {
            while (*vg == gen) { __nanosleep(32); }
        }
        __threadfence();
    }
    __syncthreads();
}
__device__ __forceinline__ void wreduce16(float a[16]) {
#pragma unroll
    for (int b = 0; b < 16; b++) {
#pragma unroll
        for (int off = 16; off; off >>= 1)
            a[b] += __shfl_xor_sync(0xffffffffu, a[b], off);
    }
}
__device__ __forceinline__ float pick16(const float a[16], int lane) {
    float r = 0.f;
#pragma unroll
    for (int b = 0; b < 16; b++) r = (lane == b) ? a[b] : r;
    return r;
}
__device__ __forceinline__ float red_gate(const u64* a, int lane) {
    float s[16];
#pragma unroll
    for (int b = 0; b < 16; b++) s[b] = upksum(a[b]);
    wreduce16(s);
    return pick16(s, lane);
}
__device__ __forceinline__ float sigmoidf_(float x) { return 1.f / (1.f + __expf(-x)); }
__device__ __forceinline__ float gate_h(float gi, float gf, float gG, float go, float& c) {
    float iv = sigmoidf_(gi), fv = sigmoidf_(gf);
    float gv = tanhf(gG), ov = sigmoidf_(go);
    c = fv * c + iv * gv;
    return ov * tanhf(c);
}

// ---------------- weight prepass (unchanged) ----------------
__global__ void __launch_bounds__(NTHR) prep_w(
    const float* __restrict__ Whh0,
    const float* __restrict__ Wih1, const float* __restrict__ Whh1,
    const float* __restrict__ Wih2, const float* __restrict__ Whh2) {
    for (u32 idx = blockIdx.x * NTHR + threadIdx.x; idx < WB_TOT; idx += gridDim.x * NTHR) {
        int l, Kh, steps; u32 base;
        if (idx < WB_B1)      { l = 0; Kh = 512;  steps = 32; base = WB_B0; }
        else if (idx < WB_B2) { l = 1; Kh = 1024; steps = 64; base = WB_B1; }
        else                  { l = 2; Kh = 1024; steps = 64; base = WB_B2; }
        u32 within = idx - base;
        int pc = 2 * steps * 128;
        int c = within / pc;   int r1 = within % pc;
        int h = r1 / (steps * 128); int r2 = r1 % (steps * 128);
        int s = r2 / 128;      int q  = r2 % 128;
        int lane = q >> 2;     int rr = (q >> 1) & 1; int e = q & 1;
        int k = h * Kh + s * 16 + (lane & 3) * 2 + 8 * rr + e;
        int n = lane >> 2;     int gate = n & 3;      int jl = n >> 2;
        int row = gate * 1024 + 2 * c + jl;
        float v;
        if (l == 0)      v = Whh0[(size_t)row * 1024 + k];
        else if (l == 1) v = (k < 1024) ? Wih1[(size_t)row * 1024 + k]
                                        : Whh1[(size_t)row * 1024 + k - 1024];
        else             v = (k < 1024) ? Wih2[(size_t)row * 1024 + k]
                                        : Whh2[(size_t)row * 1024 + k - 1024];
        g_Wb[idx] = __float2bfloat16(v);
    }
}

// ---------------- P0 (unchanged) ----------------
__global__ void __launch_bounds__(NTHR) p0_kernel(const float* __restrict__ emb,
                                                  const float* __restrict__ Wih0,
                                                  const float* __restrict__ bih0,
                                                  const float* __restrict__ bhh0) {
    __shared__ float se[16 * EMB];
    const int tid = threadIdx.x, lane = tid & 31, w = tid >> 5;
    const int v0 = blockIdx.x * 16;
    for (int i = tid; i < 16 * EMB; i += NTHR)
        se[i] = emb[(size_t)(v0 + (i >> 9)) * EMB + (i & 511)];
    __syncthreads();
    const int jbase = blockIdx.y * 1024;
    for (int j = jbase + w * 2; j < jbase + 1024; j += 16) {
        u64 aA[16], aB[16];
#pragma unroll
        for (int b = 0; b < 16; b++) { aA[b] = 0ull; aB[b] = 0ull; }
#pragma unroll
        for (int i = 0; i < EMB / 128; i++) {
            int k = 4 * lane + 128 * i;
            ulonglong2 wA = ld2u(Wih0 + (size_t)j * (EMB + ENC2D) + k);
            ulonglong2 wB = ld2u(Wih0 + (size_t)(j + 1) * (EMB + ENC2D) + k);
#pragma unroll
            for (int v = 0; v < 16; v++) {
                ulonglong2 e2 = ld2u(se + v * EMB + k);
                ffma2(aA[v], wA.x, e2.x); ffma2(aA[v], wA.y, e2.y);
                ffma2(aB[v], wB.x, e2.x); ffma2(aB[v], wB.y, e2.y);
            }
        }
        float vA = red_gate(aA, lane), vB = red_gate(aB, lane);
        if (lane < 16) {
            g_P0[(size_t)(v0 + lane) * G4 + j]     = vA + bih0[j]     + bhh0[j];
            g_P0[(size_t)(v0 + lane) * G4 + j + 1] = vB + bih0[j + 1] + bhh0[j + 1];
        }
    }
}

// ---------------- layer-parallel tensor-core recurrence ----------------
#define XSTRIDE 2064
#define XSZ     33024
#define L0OFF   99072
#define PAIROFF 101120
#define REC_SMEM 109312

// CG=true: bypass L1 (streamed weights); CG=false: L1-cacheable (L0 pinned set)
template<int STEPS, bool CG>
__device__ __forceinline__ void mma_loop(u32 addr, const __nv_bfloat16* wp, int lane,
                                         float& d0, float& d1, float& d2, float& d3) {
    d0 = d1 = d2 = d3 = 0.f;
    const u64* wq = reinterpret_cast<const u64*>(wp + lane * 4);
#pragma unroll 8
    for (int s = 0; s < STEPS; s++) {
        u32 a0, a1, a2, a3;
        asm volatile("ldmatrix.sync.aligned.m8n8.x4.shared.b16 {%0,%1,%2,%3}, [%4];"
            : "=r"(a0), "=r"(a1), "=r"(a2), "=r"(a3) : "r"(addr));
        u64 bw = CG ? __ldcg(wq + s * 32) : wq[s * 32];
        u32 b0 = (u32)bw, b1 = (u32)(bw >> 32);
        asm volatile("mma.sync.aligned.m16n8k16.row.col.f32.bf16.bf16.f32 "
            "{%0,%1,%2,%3}, {%4,%5,%6,%7}, {%8,%9}, {%0,%1,%2,%3};"
            : "+f"(d0), "+f"(d1), "+f"(d2), "+f"(d3)
            : "r"(a0), "r"(a1), "r"(a2), "r"(a3), "r"(b0), "r"(b1));
        addr += 32;
    }
}

// scatter m16n8 D frag into gg[jl][gate][b] layout (warp-local)
__device__ __forceinline__ void layout_gg(float* gg, int lane,
                                          float d0, float d1, float d2, float d3) {
    int r = lane >> 2, cc = (lane & 3) * 2;
    gg[((cc    ) >> 2) * 64 + ((cc    ) & 3) * 16 + r    ] = d0;
    gg[((cc + 1) >> 2) * 64 + ((cc + 1) & 3) * 16 + r    ] = d1;
    gg[((cc    ) >> 2) * 64 + ((cc    ) & 3) * 16 + r + 8] = d2;
    gg[((cc + 1) >> 2) * 64 + ((cc + 1) & 3) * 16 + r + 8] = d3;
    __syncwarp();
}

__device__ __forceinline__ void combine(float* pp, float* gg, int half, int lane, int barid,
                                        float d0, float d1, float d2, float d3) {
    if (half) {
        ((float4*)pp)[lane] = make_float4(d0, d1, d2, d3);
        asm volatile("bar.sync %0, 64;" :: "r"(barid) : "memory");
    } else {
        asm volatile("bar.sync %0, 64;" :: "r"(barid) : "memory");
        float4 q = ((float4*)pp)[lane];
        layout_gg(gg, lane, d0 + q.x, d1 + q.y, d2 + q.z, d3 + q.w);
    }
}

__global__ void __launch_bounds__(RTHR, 1) rec_kernel(
    const int* __restrict__ tokens,
    const float* __restrict__ bih1, const float* __restrict__ bhh1,
    const float* __restrict__ bih2, const float* __restrict__ bhh2) {
    extern __shared__ char smem[];
    const int tid = threadIdx.x, lane = tid & 31, w = tid >> 5;

    u32 sb = smem_u32(smem);
    const int arow = lane & 15;
    const int acolb = ((lane >= 16) ? 8 : 0) * 2;
    u32 xa0 = sb + arow * XSTRIDE + acolb;
    u32 xa1 = xa0 + XSZ;
    u32 xa2 = xa1 + XSZ;
    const int bL = lane & 15, jl = lane >> 4;

    for (int i = tid; i < (3 * XSZ) / 4; i += RTHR) ((u32*)smem)[i] = 0u;
    __syncthreads();

    if (w < 4) {
        // ================= L0 warps: one full chunk each, K=1024, no K-split =========
        const int chunk = blockIdx.x * 4 + w;
        const int jg = chunk * 2 + jl;
        float* gg = (float*)(smem + L0OFF + w * 512);
        const __nv_bfloat16* w0 = g_Wb + WB_B0 + (size_t)chunk * 8192;
        float c0 = 0.f;
        for (int tick = 0; tick < TSTEPS + 2; tick++) {
            if (tick <= 256) {
                float d0, d1, d2, d3;
                mma_loop<64, false>(xa0, w0, lane, d0, d1, d2, d3);
                layout_gg(gg, lane, d0, d1, d2, d3);
                int tok = (tick == 0) ? SOS_TOK : tokens[bL * 256 + tick - 1];
                const float* p = g_P0 + (size_t)tok * G4 + jg;
                float h = gate_h(gg[jl * 64 + bL] + p[0],
                                 gg[jl * 64 + 16 + bL] + p[1024],
                                 gg[jl * 64 + 32 + bL] + p[2048],
                                 gg[jl * 64 + 48 + bL] + p[3072], c0);
                g_hb[0][bL * 1024 + jg] = __float2bfloat16(h);
            }
            grid_sync();
            if (tick <= 256)
                for (int i = tid; i < 2048; i += RTHR) {
                    u64 v = __ldcg((const u64*)(g_hb[0]) + i);
                    *(u64*)(smem + (i >> 8) * XSTRIDE + (i & 255) * 8) = v;
                }
            if (tick >= 1 && tick <= 257)
                for (int i = tid; i < 2048; i += RTHR) {
                    u64 v = __ldcg((const u64*)(g_hb[1]) + i);
                    *(u64*)(smem + XSZ + (i >> 8) * XSTRIDE + (i & 255) * 8) = v;
                }
            if (tick >= 2 && tick <= 257)
                for (int i = tid; i < 2048; i += RTHR) {
                    u64 v = __ldcg((const u64*)(g_hb[2]) + i);
                    *(u64*)(smem + 2 * XSZ + (i >> 8) * XSTRIDE + (i & 255) * 8) = v;
                }
            __syncthreads();
        }
    } else if (w < 12) {
        // ================= L1 pairs =================
        const int pr = (w - 4) >> 1, half = w & 1;
        const int chunk = blockIdx.x * 4 + pr;
        const int jg = chunk * 2 + jl;
        const int barid = 1 + pr;
        float* pp = (float*)(smem + PAIROFF + pr * 1024);
        float* gg = pp + 128;
        const __nv_bfloat16* w1 = g_Wb + WB_B1 + (size_t)(chunk * 2 + half) * 8192;
        float B1g[4];
#pragma unroll
        for (int gt = 0; gt < 4; gt++)
            B1g[gt] = bih1[gt * 1024 + jg] + bhh1[gt * 1024 + jg];
        float c1 = 0.f;
        for (int tick = 0; tick < TSTEPS + 2; tick++) {
            if (tick >= 1 && tick <= 257) {
                float d0, d1, d2, d3;
                mma_loop<64, true>(half ? xa1 : xa0, w1, lane, d0, d1, d2, d3);
                combine(pp, gg, half, lane, barid, d0, d1, d2, d3);
                if (!half) {
                    float h = gate_h(gg[jl * 64 + bL] + B1g[0],
                                     gg[jl * 64 + 16 + bL] + B1g[1],
                                     gg[jl * 64 + 32 + bL] + B1g[2],
                                     gg[jl * 64 + 48 + bL] + B1g[3], c1);
                    g_hb[1][bL * 1024 + jg] = __float2bfloat16(h);
                }
            }
            grid_sync();
            if (tick <= 256)
                for (int i = tid; i < 2048; i += RTHR) {
                    u64 v = __ldcg((const u64*)(g_hb[0]) + i);
                    *(u64*)(smem + (i >> 8) * XSTRIDE + (i & 255) * 8) = v;
                }
            if (tick >= 1 && tick <= 257)
                for (int i = tid; i < 2048; i += RTHR) {
                    u64 v = __ldcg((const u64*)(g_hb[1]) + i);
                    *(u64*)(smem + XSZ + (i >> 8) * XSTRIDE + (i & 255) * 8) = v;
                }
            if (tick >= 2 && tick <= 257)
                for (int i = tid; i < 2048; i += RTHR) {
                    u64 v = __ldcg((const u64*)(g_hb[2]) + i);
                    *(u64*)(smem + 2 * XSZ + (i >> 8) * XSTRIDE + (i & 255) * 8) = v;
                }
            __syncthreads();
        }
    } else {
        // ================= L2 pairs =================
        const int pr = (w - 12) >> 1, half = w & 1;
        const int chunk = blockIdx.x * 4 + pr;
        const int jg = chunk * 2 + jl;
        const int barid = 5 + pr;
        float* pp = (float*)(smem + PAIROFF + (4 + pr) * 1024);
        float* gg = pp + 128;
        const __nv_bfloat16* w2 = g_Wb + WB_B2 + (size_t)(chunk * 2 + half) * 8192;
        float B2g[4];
#pragma unroll
        for (int gt = 0; gt < 4; gt++)
            B2g[gt] = bih2[gt * 1024 + jg] + bhh2[gt * 1024 + jg];
        float c2 = 0.f;
        for (int tick = 0; tick < TSTEPS + 2; tick++) {
            if (tick >= 2) {
                float d0, d1, d2, d3;
                mma_loop<64, true>(half ? xa2 : xa1, w2, lane, d0, d1, d2, d3);
                combine(pp, gg, half, lane, barid, d0, d1, d2, d3);
                if (!half) {
                    float h = gate_h(gg[jl * 64 + bL] + B2g[0],
                                     gg[jl * 64 + 16 + bL] + B2g[1],
                                     gg[jl * 64 + 32 + bL] + B2g[2],
                                     gg[jl * 64 + 48 + bL] + B2g[3], c2);
                    g_hb[2][bL * 1024 + jg] = __float2bfloat16(h);
                    g_hs[(size_t)(tick - 2) * (BATCH * HID) + bL * 1024 + jg] = h;
                }
            }
            grid_sync();
            if (tick <= 256)
                for (int i = tid; i < 2048; i += RTHR) {
                    u64 v = __ldcg((const u64*)(g_hb[0]) + i);
                    *(u64*)(smem + (i >> 8) * XSTRIDE + (i & 255) * 8) = v;
                }
            if (tick >= 1 && tick <= 257)
                for (int i = tid; i < 2048; i += RTHR) {
                    u64 v = __ldcg((const u64*)(g_hb[1]) + i);
                    *(u64*)(smem + XSZ + (i >> 8) * XSTRIDE + (i & 255) * 8) = v;
                }
            if (tick >= 2 && tick <= 257)
                for (int i = tid; i < 2048; i += RTHR) {
                    u64 v = __ldcg((const u64*)(g_hb[2]) + i);
                    *(u64*)(smem + 2 * XSZ + (i >> 8) * XSTRIDE + (i & 255) * 8) = v;
                }
            __syncthreads();
        }
    }
}

// ---------------- attention: scores ----------------
__global__ void __launch_bounds__(NTHR, 2) scores_kernel(const float* __restrict__ enc) {
    extern __shared__ float sm[];
    float* sh_hs = sm;                 // [16][1024]
    const int tid = threadIdx.x, lane = tid & 31, w = tid >> 5;
    const int t0 = blockIdx.x * 16, b = blockIdx.y, sc = blockIdx.z;

    for (int i = tid; i < 16 * HID; i += NTHR) {
        int t = t0 + (i >> 10);
        sh_hs[i] = (t < TSTEPS) ? g_hs[(size_t)t * (BATCH * HID) + b * HID + (i & 1023)] : 0.f;
    }
    __syncthreads();
    const float* encb = enc + (size_t)b * SEQ * ENC2D;

    const int sbase = sc * 128;
    for (int s0 = sbase + w * 2; s0 < sbase + 128; s0 += 16) {
        u64 aA[16], aB[16];
#pragma unroll
        for (int i = 0; i < 16; i++) { aA[i] = 0ull; aB[i] = 0ull; }
        const float* e0 = encb + (size_t)s0 * ENC2D;
        const float* e1 = e0 + ENC2D;
#pragma unroll 2
        for (int i = 0; i < ENC2D / 128; i++) {
            int k = 4 * lane + 128 * i;
            ulonglong2 ea = ld2u(e0 + k), eb = ld2u(e1 + k);
#pragma unroll
            for (int tt = 0; tt < 16; tt++) {
                ulonglong2 h2 = ld2u(sh_hs + tt * HID + k);
                ffma2(aA[tt], ea.x, h2.x); ffma2(aA[tt], ea.y, h2.y);
                ffma2(aB[tt], eb.x, h2.x); ffma2(aB[tt], eb.y, h2.y);
            }
        }
        float vA = red_gate(aA, lane), vB = red_gate(aB, lane);
        if (lane < 16 && t0 + lane < TSTEPS) {
            g_sc[((size_t)b * SEQ + s0) * TPAD + t0 + lane] = vA;
            g_sc[((size_t)b * SEQ + s0 + 1) * TPAD + t0 + lane] = vB;
        }
    }
}

// ---------------- attention: softmax ----------------
__global__ void __launch_bounds__(128) soft_kernel() {
    const int bx = blockIdx.x;
    const int b = bx / TSTEPS, t = bx - b * TSTEPS;
    const int tid = threadIdx.x, lane = tid & 31, w = tid >> 5;
    __shared__ float red[8];
    float v[4];
    float mx = -1e30f;
#pragma unroll
    for (int q = 0; q < 4; q++) {
        int s = tid + q * 128;
        v[q] = g_sc[((size_t)b * SEQ + s) * TPAD + t];
        mx = fmaxf(mx, v[q]);
    }
#pragma unroll
    for (int o = 16; o; o >>= 1) mx = fmaxf(mx, __shfl_xor_sync(0xffffffffu, mx, o));
    if (lane == 0) red[w] = mx;
    __syncthreads();
    mx = fmaxf(fmaxf(red[0], red[1]), fmaxf(red[2], red[3]));
    float sum = 0.f;
#pragma unroll
    for (int q = 0; q < 4; q++) { v[q] = __expf(v[q] - mx); sum += v[q]; }
#pragma unroll
    for (int o = 16; o; o >>= 1) sum += __shfl_xor_sync(0xffffffffu, sum, o);
    if (lane == 0) red[4 + w] = sum;
    __syncthreads();
    sum = red[4] + red[5] + red[6] + red[7];
    float inv = 1.f / sum;
#pragma unroll
    for (int q = 0; q < 4; q++)
        g_sc[((size_t)b * SEQ + tid + q * 128) * TPAD + t] = v[q] * inv;
}

// ---------------- attention: ctx ----------------
__global__ void __launch_bounds__(NTHR) ctx_kernel(const float* __restrict__ enc) {
    __shared__ __align__(16) float satt[SEQ * 16];   // 32 KB [s][tt]
    const int tid = threadIdx.x;
    const int t0 = blockIdx.x * 16, b = blockIdx.y, kc = blockIdx.z;

    for (int i = tid; i < SEQ * 16; i += NTHR) {
        int s = i >> 4, tt = i & 15;
        int t = t0 + tt;
        satt[i] = (t < TSTEPS) ? g_sc[((size_t)b * SEQ + s) * TPAD + t] : 0.f;
    }
    __syncthreads();

    const int k = kc * 256 + tid;
    const float* ek = enc + (size_t)b * SEQ * ENC2D + k;
    u64 acc[8];
#pragma unroll
    for (int p = 0; p < 8; p++) acc[p] = 0ull;
#pragma unroll 4
    for (int s = 0; s < SEQ; s++) {
        float ev = __ldg(ek + (size_t)s * ENC2D);
        u64 evv;
        asm("mov.b64 %0, {%1,%1};" : "=l"(evv) : "f"(ev));
        const ulonglong2* ap = (const ulonglong2*)(satt + s * 16);
        ulonglong2 q0 = ap[0], q1 = ap[1], q2 = ap[2], q3 = ap[3];
        ffma2(acc[0], evv, q0.x); ffma2(acc[1], evv, q0.y);
        ffma2(acc[2], evv, q1.x); ffma2(acc[3], evv, q1.y);
        ffma2(acc[4], evv, q2.x); ffma2(acc[5], evv, q2.y);
        ffma2(acc[6], evv, q3.x); ffma2(acc[7], evv, q3.y);
    }
#pragma unroll
    for (int p = 0; p < 8; p++) {
        float lo, hi;
        asm("mov.b64 {%0,%1}, %2;" : "=f"(lo), "=f"(hi) : "l"(acc[p]));
        int t = t0 + 2 * p;
        if (t < TSTEPS)     g_ctx[(size_t)t * (BATCH * HID) + b * HID + k] = lo;
        if (t + 1 < TSTEPS) g_ctx[(size_t)(t + 1) * (BATCH * HID) + b * HID + k] = hi;
    }
}

// ---------------- fused MLP + logits + NLL per t ----------------
__global__ void __launch_bounds__(NTHR, 1) mlp_kernel(
    const int* __restrict__ tokens,
    const float* __restrict__ W1, const float* __restrict__ b1,
    const float* __restrict__ W2, const float* __restrict__ b2) {
    extern __shared__ float sm[];
    float* sx = sm;
    float* sh = sm + 16 * 2048;
    float* red = sm + 16 * 2048 + 16 * 1024;
    const int tid = threadIdx.x, lane = tid & 31, w = tid >> 5;
    const int t = blockIdx.x;

    for (int i = tid; i < 16 * 1024; i += NTHR) {
        int b = i >> 10, k = i & 1023;
        sx[b * 2048 + k] = g_hs[(size_t)t * (BATCH * HID) + i];
        sx[b * 2048 + 1024 + k] = g_ctx[(size_t)t * (BATCH * HID) + i];
    }
    __syncthreads();

    for (int j0 = w * 4; j0 < 1024; j0 += 32) {
        u64 a0[16], a1[16], a2[16], a3[16];
#pragma unroll
        for (int b = 0; b < 16; b++) { a0[b] = a1[b] = a2[b] = a3[b] = 0ull; }
        const float* R0 = W1 + (size_t)j0 * 2048;
        const float* R1 = R0 + 2048;
        const float* R2 = R1 + 2048;
        const float* R3 = R2 + 2048;
#pragma unroll 2
        for (int i = 0; i < 2048 / 128; i++) {
            int k = 4 * lane + 128 * i;
            ulonglong2 w0 = ld2u(R0 + k), w1 = ld2u(R1 + k), w2 = ld2u(R2 + k), w3 = ld2u(R3 + k);
#pragma unroll
            for (int b = 0; b < 16; b++) {
                ulonglong2 x2 = ld2u(sx + b * 2048 + k);
                ffma2(a0[b], w0.x, x2.x); ffma2(a0[b], w0.y, x2.y);
                ffma2(a1[b], w1.x, x2.x); ffma2(a1[b], w1.y, x2.y);
                ffma2(a2[b], w2.x, x2.x); ffma2(a2[b], w2.y, x2.y);
                ffma2(a3[b], w3.x, x2.x); ffma2(a3[b], w3.y, x2.y);
            }
        }
        float v0 = red_gate(a0, lane), v1 = red_gate(a1, lane);
        float v2 = red_gate(a2, lane), v3 = red_gate(a3, lane);
        if (lane < 16) {
            sh[lane * 1024 + j0 + 0] = tanhf(v0 + b1[j0 + 0]);
            sh[lane * 1024 + j0 + 1] = tanhf(v1 + b1[j0 + 1]);
            sh[lane * 1024 + j0 + 2] = tanhf(v2 + b1[j0 + 2]);
            sh[lane * 1024 + j0 + 3] = tanhf(v3 + b1[j0 + 3]);
        }
    }
    __syncthreads();

    float M = -1e30f, S = 0.f, TV = 0.f;
    int tgt = 0;
    if (lane < 16) tgt = (t < 256) ? tokens[lane * 256 + t] : EOS_TOK;

    for (int j0 = w * 4; j0 < 1024; j0 += 32) {
        u64 a0[16], a1[16], a2[16], a3[16];
#pragma unroll
        for (int b = 0; b < 16; b++) { a0[b] = a1[b] = a2[b] = a3[b] = 0ull; }
        const float* R0 = W2 + (size_t)j0 * 1024;
        const float* R1 = R0 + 1024;
        const float* R2 = R1 + 1024;
        const float* R3 = R2 + 1024;
#pragma unroll 2
        for (int i = 0; i < 1024 / 128; i++) {
            int k = 4 * lane + 128 * i;
            ulonglong2 w0 = ld2u(R0 + k), w1 = ld2u(R1 + k), w2 = ld2u(R2 + k), w3 = ld2u(R3 + k);
#pragma unroll
            for (int b = 0; b < 16; b++) {
                ulonglong2 h2 = ld2u(sh + b * 1024 + k);
                ffma2(a0[b], w0.x, h2.x); ffma2(a0[b], w0.y, h2.y);
                ffma2(a1[b], w1.x, h2.x); ffma2(a1[b], w1.y, h2.y);
                ffma2(a2[b], w2.x, h2.x); ffma2(a2[b], w2.y, h2.y);
                ffma2(a3[b], w3.x, h2.x); ffma2(a3[b], w3.y, h2.y);
            }
        }
        float v[4];
        v[0] = red_gate(a0, lane); v[1] = red_gate(a1, lane);
        v[2] = red_gate(a2, lane); v[3] = red_gate(a3, lane);
        if (lane < 16) {
#pragma unroll
            for (int r = 0; r < 4; r++) {
                float val = v[r] + b2[j0 + r];
                float mn = fmaxf(M, val);
                S = S * __expf(M - mn) + __expf(val - mn);
                M = mn;
                if (j0 + r == tgt) TV = val;
            }
        }
    }
    if (lane < 16) {
        red[(w * 16 + lane) * 3 + 0] = M;
        red[(w * 16 + lane) * 3 + 1] = S;
        red[(w * 16 + lane) * 3 + 2] = TV;
    }
    __syncthreads();
    if (w == 0 && lane < 16) {
        float m = -1e30f, s = 0.f, tv = 0.f;
        for (int ww = 0; ww < 8; ww++) {
            float mw = red[(ww * 16 + lane) * 3 + 0];
            float sw = red[(ww * 16 + lane) * 3 + 1];
            tv += red[(ww * 16 + lane) * 3 + 2];
            float mn = fmaxf(m, mw);
            s = s * __expf(m - mn) + sw * __expf(mw - mn);
            m = mn;
        }
        float nll = (m + logf(s)) - tv;
#pragma unroll
        for (int o = 8; o; o >>= 1) nll += __shfl_xor_sync(0xffffu, nll, o);
        if (lane == 0) g_partial[t] = nll;
    }
}

__global__ void reduce_kernel(float* out) {
    __shared__ float s[256];
    int tid = threadIdx.x;
    float v = g_partial[tid];
    if (tid == 0) v += g_partial[256];
    s[tid] = v; __syncthreads();
    for (int o = 128; o; o >>= 1) { if (tid < o) s[tid] += s[tid + o]; __syncthreads(); }
    if (tid == 0) out[0] = s[0] / (float)(TSTEPS * BATCH);
}

extern "C" void kernel_launch(void* const* d_in, const int* in_sizes, int n_in,
                              void* d_out, int out_size) {
    const int*   tokens = (const int*)d_in[0];
    const float* enc    = (const float*)d_in[1];
    const float* emb    = (const float*)d_in[2];
    const float* Wih0   = (const float*)d_in[3];
    const float* Whh0   = (const float*)d_in[4];
    const float* bih0   = (const float*)d_in[5];
    const float* bhh0   = (const float*)d_in[6];
    const float* Wih1   = (const float*)d_in[7];
    const float* Whh1   = (const float*)d_in[8];
    const float* bih1   = (const float*)d_in[9];
    const float* bhh1   = (const float*)d_in[10];
    const float* Wih2   = (const float*)d_in[11];
    const float* Whh2   = (const float*)d_in[12];
    const float* bih2   = (const float*)d_in[13];
    const float* bhh2   = (const float*)d_in[14];
    const float* W1     = (const float*)d_in[15];
    const float* b1     = (const float*)d_in[16];
    const float* W2     = (const float*)d_in[17];
    const float* b2     = (const float*)d_in[18];
    float* out = (float*)d_out;

    const int SCORES_SMEM = BATCH * HID * 4;                         // 65536
    const int MLP_SMEM = (16 * 2048 + 16 * 1024 + 8 * 16 * 3) * 4;   // 198144
    cudaFuncSetAttribute(rec_kernel,    cudaFuncAttributeMaxDynamicSharedMemorySize, REC_SMEM);
    cudaFuncSetAttribute(scores_kernel, cudaFuncAttributeMaxDynamicSharedMemorySize, SCORES_SMEM);
    cudaFuncSetAttribute(mlp_kernel,    cudaFuncAttributeMaxDynamicSharedMemorySize, MLP_SMEM);

    prep_w<<<2048, NTHR>>>(Whh0, Wih1, Whh1, Wih2, Whh2);
    p0_kernel<<<dim3(64, 4), NTHR>>>(emb, Wih0, bih0, bhh0);
    rec_kernel<<<128, RTHR, REC_SMEM>>>(tokens, bih1, bhh1, bih2, bhh2);
    scores_kernel<<<dim3(17, 16, 4), NTHR, SCORES_SMEM>>>(enc);
    soft_kernel<<<16 * TSTEPS, 128>>>();
    ctx_kernel<<<dim3(17, 16, 4), NTHR>>>(enc);
    mlp_kernel<<<TSTEPS, NTHR, MLP_SMEM>>>(tokens, W1, b1, W2, b2);
    reduce_kernel<<<1, 256>>>(out);
}